// round 7
// baseline (speedup 1.0000x reference)
#include <cuda_runtime.h>
#include <cuda_bf16.h>
#include <cstdint>
#include <cfloat>
#include <math.h>

#define Bsz 1024
#define Qsz 65536
#define Dsz 512
#define MARGINf 0.4f
#define SCALEf 32.0f
#define K2f 46.166241308446828f   /* 32*log2(e) */
#define NTILE 1024                /* Qsz/64 q-tiles */
#define CPAD 133

// ---------------- static device scratch (no allocations) ----------------
__device__ __align__(16) __nv_bfloat16 g_qbf[(size_t)2 * Qsz * Dsz]; // 128 MB
__device__ __align__(16) __nv_bfloat16 g_pbf[Bsz * Dsz];             // 1 MB
__device__ float g_s1[(size_t)NTILE * Bsz];                          // 4 MB
__device__ float g_s2[(size_t)NTILE * Bsz];                          // 4 MB
__device__ float g_t1[(size_t)NTILE * (Bsz / 4) * 10];               // 10 MB
__device__ float g_t2[(size_t)NTILE * (Bsz / 4) * 10];               // 10 MB
__device__ float g_row[Bsz];

// ---------------- helpers ----------------
__device__ __forceinline__ float ex2f(float x) {
    float y;
    asm("ex2.approx.ftz.f32 %0, %1;" : "=f"(y) : "f"(x));
    return y;
}

// maintain descending sorted 10-list in registers
__device__ __forceinline__ void ins10(float (&t)[10], float v) {
    if (v <= t[9]) return;
    #pragma unroll
    for (int i = 0; i < 10; ++i) {
        float a  = t[i];
        float hi = fmaxf(a, v);
        float lo = fminf(a, v);
        t[i] = hi;
        v    = lo;
    }
}

#define MMA16816(ac, Ar, b0, b1)                                                        \
    asm volatile(                                                                       \
        "mma.sync.aligned.m16n8k16.row.col.f32.bf16.bf16.f32 "                          \
        "{%0,%1,%2,%3},{%4,%5,%6,%7},{%8,%9},{%0,%1,%2,%3};"                            \
        : "+f"(ac[0]), "+f"(ac[1]), "+f"(ac[2]), "+f"(ac[3])                            \
        : "r"(Ar[0]), "r"(Ar[1]), "r"(Ar[2]), "r"(Ar[3]), "r"(b0), "r"(b1))

// =====================================================================
// Pass 0: fp32 -> bf16 staging for p and queue
// =====================================================================
__global__ void k_convert(const float* __restrict__ p, const float* __restrict__ q) {
    int i = blockIdx.x * blockDim.x + threadIdx.x;
    const int PN4 = (Bsz * Dsz) / 4;                   // 131072 float4s of p
    const int TOT = PN4 + (2 * Qsz * Dsz) / 4;         // + 16777216 float4s of queue
    if (i >= TOT) return;
    float4 v;
    __nv_bfloat162* dst;
    if (i < PN4) {
        v   = ((const float4*)p)[i];
        dst = (__nv_bfloat162*)g_pbf + (size_t)i * 2;
    } else {
        size_t j = (size_t)i - PN4;
        v   = ((const float4*)q)[j];
        dst = (__nv_bfloat162*)g_qbf + j * 2;
    }
    dst[0] = __floats2bfloat162_rn(v.x, v.y);
    dst[1] = __floats2bfloat162_rn(v.z, v.w);
}

// =====================================================================
// Pass 1: fused dual-GEMM + per-tile sumexp / top-10 partials
// grid (8 b-tiles [fast], 1024 q-tiles), 256 threads.
// CTA: M=128 p-rows, 64 queue rows x {q0, q1} (N_eff=128), K=512 in 8 stages.
// smem: [0,256) mask ; [256,...) 2 x 36864B stages (reused as Csh 128x133 f32).
// =====================================================================
__global__ void __launch_bounds__(256) k_pass1(const float* __restrict__ maskp,
                                               const int* __restrict__ label) {
    extern __shared__ char sm_[];
    float* maskSh = (float*)sm_;
    char*  buf    = sm_ + 256;
    const int RS  = 144;          // bytes per 64-bf16 row (128 + 16 pad)
    const int ASZ = 128 * RS;     // 18432
    const int STG = 2 * ASZ;      // 36864 per stage (A tile + B tile)

    int tid = threadIdx.x, lane = tid & 31, w = tid >> 5;
    int wm = w & 3, wn = w >> 2;               // 4 x 2 warp grid
    int bx = blockIdx.x, by = blockIdx.y;

    if (tid < 64) maskSh[tid] = maskp[by * 64 + tid];

    const __nv_bfloat16* gp  = g_pbf + (size_t)bx * 128 * Dsz;
    const __nv_bfloat16* gq0 = g_qbf + (size_t)by * 64 * Dsz;
    const __nv_bfloat16* gq1 = gq0 + (size_t)Qsz * Dsz;

    uint32_t sbase = (uint32_t)__cvta_generic_to_shared(buf);

    float acc[2][8][4];
    #pragma unroll
    for (int mt = 0; mt < 2; ++mt)
        #pragma unroll
        for (int nt = 0; nt < 8; ++nt)
            #pragma unroll
            for (int j = 0; j < 4; ++j) acc[mt][nt][j] = 0.f;

    auto issue = [&](int ks, int s) {
        uint32_t ab = sbase + s * STG;
        uint32_t bb = ab + ASZ;
        const __nv_bfloat16* gA = gp + ks * 64;
        #pragma unroll
        for (int t = 0; t < 4; ++t) {          // A: 128 rows x 8 x 16B
            int i = tid + t * 256;
            int r = i >> 3, c = i & 7;
            uint32_t d = ab + r * RS + c * 16;
            const void* src = gA + (size_t)r * Dsz + c * 8;
            asm volatile("cp.async.cg.shared.global [%0],[%1],16;" :: "r"(d), "l"(src));
        }
        #pragma unroll
        for (int t = 0; t < 4; ++t) {          // B: rows 0..63 = q0, 64..127 = q1
            int i = tid + t * 256;
            int r = i >> 3, c = i & 7;
            const __nv_bfloat16* src =
                (r < 64) ? (gq0 + (size_t)r * Dsz + ks * 64 + c * 8)
                         : (gq1 + (size_t)(r - 64) * Dsz + ks * 64 + c * 8);
            uint32_t d = bb + r * RS + c * 16;
            asm volatile("cp.async.cg.shared.global [%0],[%1],16;" :: "r"(d), "l"(src));
        }
        asm volatile("cp.async.commit_group;");
    };

    auto compute = [&](int s) {
        uint32_t ab = sbase + s * STG;
        uint32_t bb = ab + ASZ;
        uint32_t aBase = ab + (wm * 32 + (lane & 15)) * RS + (lane >> 4) * 16;
        int bq = lane >> 3;
        uint32_t bPart = bb + (wn * 64 + (bq >> 1) * 8 + (lane & 7)) * RS + (bq & 1) * 16;
        #pragma unroll
        for (int kk = 0; kk < 4; ++kk) {
            uint32_t A[2][4];
            #pragma unroll
            for (int mt = 0; mt < 2; ++mt) {
                uint32_t ad = aBase + mt * 16 * RS + kk * 32;
                asm volatile("ldmatrix.sync.aligned.m8n8.x4.shared.b16 {%0,%1,%2,%3},[%4];"
                             : "=r"(A[mt][0]), "=r"(A[mt][1]), "=r"(A[mt][2]), "=r"(A[mt][3])
                             : "r"(ad));
            }
            #pragma unroll
            for (int np = 0; np < 4; ++np) {
                uint32_t bd = bPart + np * 16 * RS + kk * 32;
                uint32_t B0, B1, B2, B3;
                asm volatile("ldmatrix.sync.aligned.m8n8.x4.shared.b16 {%0,%1,%2,%3},[%4];"
                             : "=r"(B0), "=r"(B1), "=r"(B2), "=r"(B3) : "r"(bd));
                #pragma unroll
                for (int mt = 0; mt < 2; ++mt) {
                    MMA16816(acc[mt][2 * np],     A[mt], B0, B1);
                    MMA16816(acc[mt][2 * np + 1], A[mt], B2, B3);
                }
            }
        }
    };

    issue(0, 0);
    for (int ks = 0; ks < 8; ++ks) {
        if (ks < 7) {
            issue(ks + 1, (ks + 1) & 1);
            asm volatile("cp.async.wait_group 1;");
        } else {
            asm volatile("cp.async.wait_group 0;");
        }
        __syncthreads();
        compute(ks & 1);
        __syncthreads();
    }

    // ---- write C tile to smem (reuse stage buffers; 128*133*4 = 68096 B fits) ----
    float* Csh = (float*)buf;
    #pragma unroll
    for (int mt = 0; mt < 2; ++mt)
        #pragma unroll
        for (int nt = 0; nt < 8; ++nt) {
            int r = wm * 32 + mt * 16 + (lane >> 2);
            int c = wn * 64 + nt * 8 + 2 * (lane & 3);
            Csh[r * CPAD + c]           = acc[mt][nt][0];
            Csh[r * CPAD + c + 1]       = acc[mt][nt][1];
            Csh[(r + 8) * CPAD + c]     = acc[mt][nt][2];
            Csh[(r + 8) * CPAD + c + 1] = acc[mt][nt][3];
        }
    __syncthreads();

    // ---- fused epilogue: tid<128 -> cos1 row tid ; tid>=128 -> cos2 row tid-128 ----
    int  r   = tid & 127;
    bool m2  = (tid >= 128);
    int  gb  = bx * 128 + r;
    bool neg = (label[gb] == -1);

    float s = 0.f;
    float top[10];
    #pragma unroll
    for (int i = 0; i < 10; ++i) top[i] = -FLT_MAX;

    const float* Crow = Csh + r * CPAD;
    for (int c = 0; c < 64; ++c) {
        float v;
        if (!m2) v = Crow[c];
        else     v = (maskSh[c] != 0.f) ? Crow[64 + c] : Crow[c];
        s += ex2f(K2f * v);
        if (neg) ins10(top, v);
    }

    size_t si = (size_t)by * Bsz + gb;
    if (!m2) g_s1[si] = s; else g_s2[si] = s;
    if (neg) {
        size_t ti = ((size_t)by * 256 + (gb >> 2)) * 10;
        float* gt_ = m2 ? g_t2 : g_t1;
        #pragma unroll
        for (int i = 0; i < 10; ++i) gt_[ti + i] = top[i];
    }
}

// =====================================================================
// Pass 2: per-row merge. Pos rows: sumexp merge + margin correction +
// exact fp32 gt dots. Neg rows: merge 1024 top-10 lists -> top-10 -> mean.
// grid 1024 blocks x 256 threads.
// =====================================================================
__global__ void __launch_bounds__(256) k_pass2(const float* __restrict__ p,
                                               const float* __restrict__ q,
                                               const float* __restrict__ maskp,
                                               const int* __restrict__ label) {
    __shared__ float red[256];
    __shared__ float red2[256];
    __shared__ float cand[2560];
    __shared__ float wv_[8];
    __shared__ int   wi_[8];

    int b = blockIdx.x, tid = threadIdx.x;
    int lab = label[b];

    if (lab != -1) {
        // ---- sumexp merge across tiles ----
        float s1 = 0.f, s2 = 0.f;
        for (int t = tid; t < NTILE; t += 256) {
            s1 += g_s1[(size_t)t * Bsz + b];
            s2 += g_s2[(size_t)t * Bsz + b];
        }
        red[tid] = s1; red2[tid] = s2;
        __syncthreads();
        for (int o = 128; o > 0; o >>= 1) {
            if (tid < o) { red[tid] += red[tid + o]; red2[tid] += red2[tid + o]; }
            __syncthreads();
        }
        float S1 = red[0], S2 = red2[0];
        __syncthreads();

        // ---- exact fp32 ground-truth dot products ----
        float d1 = 0.f, d2 = 0.f;
        float mk = maskp[lab];
        const float* pr = p + (size_t)b * Dsz;
        const float* q0 = q + (size_t)lab * Dsz;
        const float* q1 = q0 + (size_t)Qsz * Dsz;
        for (int d = tid; d < Dsz; d += 256) {
            float pv = pr[d], a0 = q0[d], a1 = q1[d];
            float wv = mk * a1 + (1.f - mk) * a0;
            d1 += pv * a0;
            d2 += pv * wv;
        }
        red[tid] = d1; red2[tid] = d2;
        __syncthreads();
        for (int o = 128; o > 0; o >>= 1) {
            if (tid < o) { red[tid] += red[tid + o]; red2[tid] += red2[tid + o]; }
            __syncthreads();
        }
        if (tid == 0) {
            float gt1 = red[0], gt2 = red2[0];
            float sp1 = S1 - ex2f(K2f * gt1) + ex2f(K2f * (gt1 - MARGINf));
            float sp2 = S2 - ex2f(K2f * gt2) + ex2f(K2f * (gt2 - MARGINf));
            float ce1 = logf(sp1) - (gt1 - MARGINf) * SCALEf;
            float ce2 = logf(sp2) - (gt2 - MARGINf) * SCALEf;
            g_row[b] = ce1 + ce2;
        }
    } else {
        // ---- hard-negative top-10 merge, both matrices ----
        float negsum = 0.f;   // only thread 0's copy matters
        size_t base = (size_t)(b >> 2) * 10;
        for (int mat = 0; mat < 2; ++mat) {
            const float* gt_ = mat ? g_t2 : g_t1;
            float top[10];
            #pragma unroll
            for (int i = 0; i < 10; ++i) top[i] = -FLT_MAX;
            for (int t = tid; t < NTILE; t += 256) {
                const float* L = gt_ + (size_t)t * (256 * 10) + base;
                #pragma unroll
                for (int i = 0; i < 10; ++i) {
                    float v = L[i];
                    if (v <= top[9]) break;   // lists are sorted descending
                    ins10(top, v);
                }
            }
            #pragma unroll
            for (int i = 0; i < 10; ++i) cand[tid * 10 + i] = top[i];
            __syncthreads();

            for (int it = 0; it < 10; ++it) {
                float bv = -FLT_MAX; int bi = -1;
                #pragma unroll
                for (int j = 0; j < 10; ++j) {
                    float v = cand[tid * 10 + j];
                    if (v > bv) { bv = v; bi = tid * 10 + j; }
                }
                #pragma unroll
                for (int o = 16; o > 0; o >>= 1) {
                    float ov = __shfl_down_sync(0xffffffffu, bv, o);
                    int   oi = __shfl_down_sync(0xffffffffu, bi, o);
                    if (ov > bv) { bv = ov; bi = oi; }
                }
                if ((tid & 31) == 0) { wv_[tid >> 5] = bv; wi_[tid >> 5] = bi; }
                __syncthreads();
                if (tid == 0) {
                    float mv = wv_[0]; int mi = wi_[0];
                    #pragma unroll
                    for (int k = 1; k < 8; ++k)
                        if (wv_[k] > mv) { mv = wv_[k]; mi = wi_[k]; }
                    cand[mi] = -FLT_MAX;
                    negsum += fmaxf(mv, 0.f);
                }
                __syncthreads();
            }
            __syncthreads();
        }
        if (tid == 0) g_row[b] = negsum * 0.1f;   // mean over 10, summed over mats
    }
}

// =====================================================================
// Pass 3: scalar reduction
// =====================================================================
__global__ void k_final(const int* __restrict__ label, float* __restrict__ out) {
    __shared__ float sp[256], sn[256];
    __shared__ int   cp_[256], cn_[256];
    int tid = threadIdx.x;
    float ps = 0.f, ns = 0.f;
    int pc = 0, nc = 0;
    for (int b = tid; b < Bsz; b += 256) {
        if (label[b] != -1) { ps += g_row[b]; pc++; }
        else                { ns += g_row[b]; nc++; }
    }
    sp[tid] = ps; sn[tid] = ns; cp_[tid] = pc; cn_[tid] = nc;
    __syncthreads();
    for (int o = 128; o > 0; o >>= 1) {
        if (tid < o) {
            sp[tid] += sp[tid + o]; sn[tid] += sn[tid + o];
            cp_[tid] += cp_[tid + o]; cn_[tid] += cn_[tid + o];
        }
        __syncthreads();
    }
    if (tid == 0) {
        float r = 0.f;
        if (cp_[0] > 0) r += sp[0] / (float)cp_[0];
        if (cn_[0] > 0) r += sn[0] / (float)cn_[0];
        out[0] = r;
    }
}

// =====================================================================
extern "C" void kernel_launch(void* const* d_in, const int* in_sizes, int n_in,
                              void* d_out, int out_size) {
    const float* p   = (const float*)d_in[0];
    const float* q   = (const float*)d_in[1];
    const float* mk  = (const float*)d_in[2];
    const int*   lab = (const int*)d_in[3];
    float* out = (float*)d_out;

    const int SMEM1 = 256 + 2 * 36864;   // 73984
    cudaFuncSetAttribute(k_pass1, cudaFuncAttributeMaxDynamicSharedMemorySize, SMEM1);

    k_convert<<<66048, 256>>>(p, q);
    dim3 g1(8, NTILE);
    k_pass1<<<g1, 256, SMEM1>>>(mk, lab);
    k_pass2<<<Bsz, 256>>>(p, q, mk, lab);
    k_final<<<1, 256>>>(lab, out);
}

// round 9
// speedup vs baseline: 1.2159x; 1.2159x over previous
#include <cuda_runtime.h>
#include <cuda_bf16.h>
#include <cstdint>
#include <cfloat>
#include <math.h>

#define Bsz 1024
#define Qsz 65536
#define Dsz 512
#define MARGINf 0.4f
#define SCALEf 32.0f
#define K2f 46.166241308446828f   /* 32*log2(e) */
#define NT2 512                   /* q-tiles of 128 slots (q0 GEMM) */
#define MT2 64                    /* masked-compact tiles of 128 */
#define MCAP 8192                 /* capacity for masked slots (~6.5K expected) */
#define CPAD 133

// ---------------- static device scratch (no allocations) ----------------
__device__ __align__(16) __nv_bfloat16 g_qbf[(size_t)Qsz * Dsz];     // q0 bf16, 64 MB
__device__ __align__(16) __nv_bfloat16 g_pbf[Bsz * Dsz];             // 1 MB
__device__ __align__(16) __nv_bfloat16 g_qm[(size_t)MCAP * Dsz];     // masked q1 rows, 8 MB
__device__ int   g_midx[MCAP];
__device__ int   g_mcount;
__device__ float g_s1 [(size_t)NT2 * Bsz];                           // sumexp cos1 (all cols)
__device__ float g_s1m[(size_t)NT2 * Bsz];                           // sumexp cos1 (masked cols)
__device__ float g_s2b[(size_t)MT2 * Bsz];                           // sumexp cos2 (masked cols)
__device__ float g_t1 [(size_t)NT2 * 256 * 10];                      // top10 cos1 all
__device__ float g_t1u[(size_t)NT2 * 256 * 10];                      // top10 cos1 unmasked
__device__ float g_t2b[(size_t)MT2 * 256 * 10];                      // top10 cos2 masked
__device__ float g_row[Bsz];

// ---------------- helpers ----------------
__device__ __forceinline__ float ex2f(float x) {
    float y;
    asm("ex2.approx.ftz.f32 %0, %1;" : "=f"(y) : "f"(x));
    return y;
}

__device__ __forceinline__ void ins10(float (&t)[10], float v) {
    if (v <= t[9]) return;
    #pragma unroll
    for (int i = 0; i < 10; ++i) {
        float a  = t[i];
        float hi = fmaxf(a, v);
        float lo = fminf(a, v);
        t[i] = hi;
        v    = lo;
    }
}

#define MMA16816(ac, Ar, b0, b1)                                                        \
    asm volatile(                                                                       \
        "mma.sync.aligned.m16n8k16.row.col.f32.bf16.bf16.f32 "                          \
        "{%0,%1,%2,%3},{%4,%5,%6,%7},{%8,%9},{%0,%1,%2,%3};"                            \
        : "+f"(ac[0]), "+f"(ac[1]), "+f"(ac[2]), "+f"(ac[3])                            \
        : "r"(Ar[0]), "r"(Ar[1]), "r"(Ar[2]), "r"(Ar[3]), "r"(b0), "r"(b1))

// =====================================================================
// Pass 0a: fp32 -> bf16 staging for p and queue[0]
// =====================================================================
__global__ void k_convert(const float* __restrict__ p, const float* __restrict__ q) {
    int i = blockIdx.x * blockDim.x + threadIdx.x;
    const int PN4 = (Bsz * Dsz) / 4;                 // 131072
    const int TOT = PN4 + (Qsz * Dsz) / 4;           // + 8388608
    if (i >= TOT) return;
    float4 v;
    __nv_bfloat162* dst;
    if (i < PN4) {
        v   = ((const float4*)p)[i];
        dst = (__nv_bfloat162*)g_pbf + (size_t)i * 2;
    } else {
        size_t j = (size_t)i - PN4;
        v   = ((const float4*)q)[j];                 // queue[0]
        dst = (__nv_bfloat162*)g_qbf + j * 2;
    }
    dst[0] = __floats2bfloat162_rn(v.x, v.y);
    dst[1] = __floats2bfloat162_rn(v.z, v.w);
}

// =====================================================================
// Pass 0b: compact masked slot indices (1 block, 1024 threads)
// =====================================================================
__global__ void __launch_bounds__(1024) k_scan(const float* __restrict__ maskp) {
    __shared__ int cnt[1024];
    int t = threadIdx.x;
    int local = 0;
    #pragma unroll 4
    for (int i = 0; i < 64; ++i) local += (maskp[t * 64 + i] != 0.f);
    cnt[t] = local;
    __syncthreads();
    for (int o = 1; o < 1024; o <<= 1) {
        int v = (t >= o) ? cnt[t - o] : 0;
        __syncthreads();
        cnt[t] += v;
        __syncthreads();
    }
    if (t == 1023) g_mcount = cnt[1023] < MCAP ? cnt[1023] : MCAP;
    int j = cnt[t] - local;
    for (int i = 0; i < 64; ++i)
        if (maskp[t * 64 + i] != 0.f) {
            if (j < MCAP) g_midx[j] = t * 64 + i;
            ++j;
        }
}

// =====================================================================
// Pass 0c: gather+convert masked q1 rows (zero-fill rows beyond count)
// grid MCAP blocks x 128 threads
// =====================================================================
__global__ void __launch_bounds__(128) k_gather(const float* __restrict__ q) {
    int j = blockIdx.x, t = threadIdx.x;
    int count = g_mcount;
    __nv_bfloat162* dst = (__nv_bfloat162*)(g_qm + (size_t)j * Dsz);
    if (j < count) {
        const float4* src =
            (const float4*)(q + (size_t)Qsz * Dsz + (size_t)g_midx[j] * Dsz);
        float4 v = src[t];
        dst[t * 2]     = __floats2bfloat162_rn(v.x, v.y);
        dst[t * 2 + 1] = __floats2bfloat162_rn(v.z, v.w);
    } else {
        __nv_bfloat162 z = __floats2bfloat162_rn(0.f, 0.f);
        dst[t * 2]     = z;
        dst[t * 2 + 1] = z;
    }
}

// =====================================================================
// Pass 1: q0 GEMM + fused epilogue (sumexp all, sumexp masked, top10 all,
// top10 unmasked).  grid (8 b-tiles [fast], 512 q-tiles), 256 threads.
// CTA tile: M=128 p-rows x N=128 q0-rows, K=512 in 8 stages of 64.
// smem: [0,512) mask[128] ; [512,...) 2 x 36864B stages (reused as Csh).
// =====================================================================
__global__ void __launch_bounds__(256) k_pass1(const float* __restrict__ maskp,
                                               const int* __restrict__ label) {
    extern __shared__ char sm_[];
    float* maskSh = (float*)sm_;
    char*  buf    = sm_ + 512;
    const int RS  = 144;
    const int ASZ = 128 * RS;     // 18432
    const int STG = 2 * ASZ;      // 36864

    int tid = threadIdx.x, lane = tid & 31, w = tid >> 5;
    int wm = w & 3, wn = w >> 2;
    int bx = blockIdx.x, by = blockIdx.y;

    if (tid < 128) maskSh[tid] = maskp[by * 128 + tid];

    const __nv_bfloat16* gp = g_pbf + (size_t)bx * 128 * Dsz;
    const __nv_bfloat16* gq = g_qbf + (size_t)by * 128 * Dsz;

    uint32_t sbase = (uint32_t)__cvta_generic_to_shared(buf);

    float acc[2][8][4];
    #pragma unroll
    for (int mt = 0; mt < 2; ++mt)
        #pragma unroll
        for (int nt = 0; nt < 8; ++nt)
            #pragma unroll
            for (int j = 0; j < 4; ++j) acc[mt][nt][j] = 0.f;

    auto issue = [&](int ks, int s) {
        uint32_t ab = sbase + s * STG;
        uint32_t bb = ab + ASZ;
        #pragma unroll
        for (int t = 0; t < 4; ++t) {          // A: 128 rows x 8 x 16B
            int i = tid + t * 256;
            int r = i >> 3, c = i & 7;
            uint32_t d = ab + r * RS + c * 16;
            const void* src = gp + (size_t)r * Dsz + ks * 64 + c * 8;
            asm volatile("cp.async.cg.shared.global [%0],[%1],16;" :: "r"(d), "l"(src));
        }
        #pragma unroll
        for (int t = 0; t < 4; ++t) {          // B: 128 q0 rows
            int i = tid + t * 256;
            int r = i >> 3, c = i & 7;
            uint32_t d = bb + r * RS + c * 16;
            const void* src = gq + (size_t)r * Dsz + ks * 64 + c * 8;
            asm volatile("cp.async.cg.shared.global [%0],[%1],16;" :: "r"(d), "l"(src));
        }
        asm volatile("cp.async.commit_group;");
    };

    auto compute = [&](int s) {
        uint32_t ab = sbase + s * STG;
        uint32_t bb = ab + ASZ;
        uint32_t aBase = ab + (wm * 32 + (lane & 15)) * RS + (lane >> 4) * 16;
        int bq = lane >> 3;
        uint32_t bPart = bb + (wn * 64 + (bq >> 1) * 8 + (lane & 7)) * RS + (bq & 1) * 16;
        #pragma unroll
        for (int kk = 0; kk < 4; ++kk) {
            uint32_t A[2][4];
            #pragma unroll
            for (int mt = 0; mt < 2; ++mt) {
                uint32_t ad = aBase + mt * 16 * RS + kk * 32;
                asm volatile("ldmatrix.sync.aligned.m8n8.x4.shared.b16 {%0,%1,%2,%3},[%4];"
                             : "=r"(A[mt][0]), "=r"(A[mt][1]), "=r"(A[mt][2]), "=r"(A[mt][3])
                             : "r"(ad));
            }
            #pragma unroll
            for (int np = 0; np < 4; ++np) {
                uint32_t bd = bPart + np * 16 * RS + kk * 32;
                uint32_t B0, B1, B2, B3;
                asm volatile("ldmatrix.sync.aligned.m8n8.x4.shared.b16 {%0,%1,%2,%3},[%4];"
                             : "=r"(B0), "=r"(B1), "=r"(B2), "=r"(B3) : "r"(bd));
                #pragma unroll
                for (int mt = 0; mt < 2; ++mt) {
                    MMA16816(acc[mt][2 * np],     A[mt], B0, B1);
                    MMA16816(acc[mt][2 * np + 1], A[mt], B2, B3);
                }
            }
        }
    };

    issue(0, 0);
    for (int ks = 0; ks < 8; ++ks) {
        if (ks < 7) {
            issue(ks + 1, (ks + 1) & 1);
            asm volatile("cp.async.wait_group 1;");
        } else {
            asm volatile("cp.async.wait_group 0;");
        }
        __syncthreads();
        compute(ks & 1);
        __syncthreads();
    }

    // ---- C tile -> smem (68096 B <= 73728 B stage region) ----
    float* Csh = (float*)buf;
    #pragma unroll
    for (int mt = 0; mt < 2; ++mt)
        #pragma unroll
        for (int nt = 0; nt < 8; ++nt) {
            int r = wm * 32 + mt * 16 + (lane >> 2);
            int c = wn * 64 + nt * 8 + 2 * (lane & 3);
            Csh[r * CPAD + c]           = acc[mt][nt][0];
            Csh[r * CPAD + c + 1]       = acc[mt][nt][1];
            Csh[(r + 8) * CPAD + c]     = acc[mt][nt][2];
            Csh[(r + 8) * CPAD + c + 1] = acc[mt][nt][3];
        }
    __syncthreads();

    // ---- fused epilogue ----
    // tid<128  : row r -> s1 (all cols) + top10 all (t1)
    // tid>=128 : row r -> s1m (masked-col sumexp) + top10 unmasked (t1u)
    int  r    = tid & 127;
    bool roleB = (tid >= 128);
    int  gb   = bx * 128 + r;
    bool neg  = (label[gb] == -1);

    float s = 0.f;
    float top[10];
    #pragma unroll
    for (int i = 0; i < 10; ++i) top[i] = -FLT_MAX;

    const float* Crow = Csh + r * CPAD;
    for (int c = 0; c < 128; ++c) {
        float v = Crow[c];
        bool  mskd = (maskSh[c] != 0.f);
        if (!roleB) {
            s += ex2f(K2f * v);
            if (neg) ins10(top, v);
        } else {
            if (mskd) s += ex2f(K2f * v);
            else if (neg) ins10(top, v);
        }
    }

    size_t si = (size_t)by * Bsz + gb;
    if (!roleB) g_s1[si] = s; else g_s1m[si] = s;
    if (neg) {
        size_t ti = ((size_t)by * 256 + (gb >> 2)) * 10;
        float* gt_ = roleB ? g_t1u : g_t1;
        #pragma unroll
        for (int i = 0; i < 10; ++i) gt_[ti + i] = top[i];
    }
}

// =====================================================================
// Pass 1b: masked GEMM p x qm^T + fused epilogue (sumexp + top10 of cos2
// over masked cols).  grid (8, 64), 256 threads. Early-exit beyond count.
// =====================================================================
__global__ void __launch_bounds__(256) k_pass1b(const int* __restrict__ label) {
    extern __shared__ char sm_[];
    char* buf = sm_ + 512;
    const int RS  = 144;
    const int ASZ = 128 * RS;
    const int STG = 2 * ASZ;

    int tid = threadIdx.x, lane = tid & 31, w = tid >> 5;
    int wm = w & 3, wn = w >> 2;
    int bx = blockIdx.x, by = blockIdx.y;
    int count = g_mcount;
    int jb = by * 128;

    if (jb >= count) {                       // dead tile: publish neutral partials
        if (bx == 0) {
            for (int r = tid; r < Bsz; r += 256) g_s2b[(size_t)by * Bsz + r] = 0.f;
            for (int i = tid; i < 2560; i += 256) g_t2b[(size_t)by * 2560 + i] = -FLT_MAX;
        }
        return;
    }

    const __nv_bfloat16* gp = g_pbf + (size_t)bx * 128 * Dsz;
    const __nv_bfloat16* gq = g_qm + (size_t)jb * Dsz;

    uint32_t sbase = (uint32_t)__cvta_generic_to_shared(buf);

    float acc[2][8][4];
    #pragma unroll
    for (int mt = 0; mt < 2; ++mt)
        #pragma unroll
        for (int nt = 0; nt < 8; ++nt)
            #pragma unroll
            for (int j = 0; j < 4; ++j) acc[mt][nt][j] = 0.f;

    auto issue = [&](int ks, int s) {
        uint32_t ab = sbase + s * STG;
        uint32_t bb = ab + ASZ;
        #pragma unroll
        for (int t = 0; t < 4; ++t) {
            int i = tid + t * 256;
            int r = i >> 3, c = i & 7;
            uint32_t d = ab + r * RS + c * 16;
            const void* src = gp + (size_t)r * Dsz + ks * 64 + c * 8;
            asm volatile("cp.async.cg.shared.global [%0],[%1],16;" :: "r"(d), "l"(src));
        }
        #pragma unroll
        for (int t = 0; t < 4; ++t) {
            int i = tid + t * 256;
            int r = i >> 3, c = i & 7;
            uint32_t d = bb + r * RS + c * 16;
            const void* src = gq + (size_t)r * Dsz + ks * 64 + c * 8;
            asm volatile("cp.async.cg.shared.global [%0],[%1],16;" :: "r"(d), "l"(src));
        }
        asm volatile("cp.async.commit_group;");
    };

    auto compute = [&](int s) {
        uint32_t ab = sbase + s * STG;
        uint32_t bb = ab + ASZ;
        uint32_t aBase = ab + (wm * 32 + (lane & 15)) * RS + (lane >> 4) * 16;
        int bq = lane >> 3;
        uint32_t bPart = bb + (wn * 64 + (bq >> 1) * 8 + (lane & 7)) * RS + (bq & 1) * 16;
        #pragma unroll
        for (int kk = 0; kk < 4; ++kk) {
            uint32_t A[2][4];
            #pragma unroll
            for (int mt = 0; mt < 2; ++mt) {
                uint32_t ad = aBase + mt * 16 * RS + kk * 32;
                asm volatile("ldmatrix.sync.aligned.m8n8.x4.shared.b16 {%0,%1,%2,%3},[%4];"
                             : "=r"(A[mt][0]), "=r"(A[mt][1]), "=r"(A[mt][2]), "=r"(A[mt][3])
                             : "r"(ad));
            }
            #pragma unroll
            for (int np = 0; np < 4; ++np) {
                uint32_t bd = bPart + np * 16 * RS + kk * 32;
                uint32_t B0, B1, B2, B3;
                asm volatile("ldmatrix.sync.aligned.m8n8.x4.shared.b16 {%0,%1,%2,%3},[%4];"
                             : "=r"(B0), "=r"(B1), "=r"(B2), "=r"(B3) : "r"(bd));
                #pragma unroll
                for (int mt = 0; mt < 2; ++mt) {
                    MMA16816(acc[mt][2 * np],     A[mt], B0, B1);
                    MMA16816(acc[mt][2 * np + 1], A[mt], B2, B3);
                }
            }
        }
    };

    issue(0, 0);
    for (int ks = 0; ks < 8; ++ks) {
        if (ks < 7) {
            issue(ks + 1, (ks + 1) & 1);
            asm volatile("cp.async.wait_group 1;");
        } else {
            asm volatile("cp.async.wait_group 0;");
        }
        __syncthreads();
        compute(ks & 1);
        __syncthreads();
    }

    float* Csh = (float*)buf;
    #pragma unroll
    for (int mt = 0; mt < 2; ++mt)
        #pragma unroll
        for (int nt = 0; nt < 8; ++nt) {
            int r = wm * 32 + mt * 16 + (lane >> 2);
            int c = wn * 64 + nt * 8 + 2 * (lane & 3);
            Csh[r * CPAD + c]           = acc[mt][nt][0];
            Csh[r * CPAD + c + 1]       = acc[mt][nt][1];
            Csh[(r + 8) * CPAD + c]     = acc[mt][nt][2];
            Csh[(r + 8) * CPAD + c + 1] = acc[mt][nt][3];
        }
    __syncthreads();

    if (tid < 128) {
        int  r   = tid;
        int  gb  = bx * 128 + r;
        bool neg = (label[gb] == -1);
        int  nvalid = count - jb; if (nvalid > 128) nvalid = 128;

        float s = 0.f;
        float top[10];
        #pragma unroll
        for (int i = 0; i < 10; ++i) top[i] = -FLT_MAX;

        const float* Crow = Csh + r * CPAD;
        for (int c = 0; c < nvalid; ++c) {
            float v = Crow[c];
            s += ex2f(K2f * v);
            if (neg) ins10(top, v);
        }
        g_s2b[(size_t)by * Bsz + gb] = s;
        if (neg) {
            size_t ti = ((size_t)by * 256 + (gb >> 2)) * 10;
            #pragma unroll
            for (int i = 0; i < 10; ++i) g_t2b[ti + i] = top[i];
        }
    }
}

// =====================================================================
// Pass 2: per-row merge
// =====================================================================
__global__ void __launch_bounds__(256) k_pass2(const float* __restrict__ p,
                                               const float* __restrict__ q,
                                               const float* __restrict__ maskp,
                                               const int* __restrict__ label) {
    __shared__ float red[256];
    __shared__ float red2[256];
    __shared__ float red3[256];
    __shared__ float cand[2560];
    __shared__ float wv_[8];
    __shared__ int   wi_[8];

    int b = blockIdx.x, tid = threadIdx.x;
    int lab = label[b];

    if (lab != -1) {
        float s1 = 0.f, s1m = 0.f, s2b = 0.f;
        for (int t = tid; t < NT2; t += 256) {
            s1  += g_s1 [(size_t)t * Bsz + b];
            s1m += g_s1m[(size_t)t * Bsz + b];
            if (t < MT2) s2b += g_s2b[(size_t)t * Bsz + b];
        }
        red[tid] = s1; red2[tid] = s1m; red3[tid] = s2b;
        __syncthreads();
        for (int o = 128; o > 0; o >>= 1) {
            if (tid < o) {
                red[tid]  += red[tid + o];
                red2[tid] += red2[tid + o];
                red3[tid] += red3[tid + o];
            }
            __syncthreads();
        }
        float S1 = red[0];
        float S2 = red[0] - red2[0] + red3[0];
        __syncthreads();

        float d1 = 0.f, d2 = 0.f;
        float mk = maskp[lab];
        const float* pr = p + (size_t)b * Dsz;
        const float* q0 = q + (size_t)lab * Dsz;
        const float* q1 = q0 + (size_t)Qsz * Dsz;
        for (int d = tid; d < Dsz; d += 256) {
            float pv = pr[d], a0 = q0[d], a1 = q1[d];
            float wv = mk * a1 + (1.f - mk) * a0;
            d1 += pv * a0;
            d2 += pv * wv;
        }
        red[tid] = d1; red2[tid] = d2;
        __syncthreads();
        for (int o = 128; o > 0; o >>= 1) {
            if (tid < o) { red[tid] += red[tid + o]; red2[tid] += red2[tid + o]; }
            __syncthreads();
        }
        if (tid == 0) {
            float gt1 = red[0], gt2 = red2[0];
            float sp1 = S1 - ex2f(K2f * gt1) + ex2f(K2f * (gt1 - MARGINf));
            float sp2 = S2 - ex2f(K2f * gt2) + ex2f(K2f * (gt2 - MARGINf));
            float ce1 = logf(sp1) - (gt1 - MARGINf) * SCALEf;
            float ce2 = logf(sp2) - (gt2 - MARGINf) * SCALEf;
            g_row[b] = ce1 + ce2;
        }
    } else {
        float negsum = 0.f;
        size_t base = (size_t)(b >> 2) * 10;
        for (int mat = 0; mat < 2; ++mat) {
            float top[10];
            #pragma unroll
            for (int i = 0; i < 10; ++i) top[i] = -FLT_MAX;
            int nlists = (mat == 0) ? NT2 : (NT2 + MT2);
            for (int t = tid; t < nlists; t += 256) {
                const float* L;
                if (mat == 0)        L = g_t1  + (size_t)t * 2560 + base;
                else if (t < NT2)    L = g_t1u + (size_t)t * 2560 + base;
                else                 L = g_t2b + (size_t)(t - NT2) * 2560 + base;
                #pragma unroll
                for (int i = 0; i < 10; ++i) {
                    float v = L[i];
                    if (v <= top[9]) break;   // sorted descending
                    ins10(top, v);
                }
            }
            #pragma unroll
            for (int i = 0; i < 10; ++i) cand[tid * 10 + i] = top[i];
            __syncthreads();

            for (int it = 0; it < 10; ++it) {
                float bv = -FLT_MAX; int bi = -1;
                #pragma unroll
                for (int j = 0; j < 10; ++j) {
                    float v = cand[tid * 10 + j];
                    if (v > bv) { bv = v; bi = tid * 10 + j; }
                }
                #pragma unroll
                for (int o = 16; o > 0; o >>= 1) {
                    float ov = __shfl_down_sync(0xffffffffu, bv, o);
                    int   oi = __shfl_down_sync(0xffffffffu, bi, o);
                    if (ov > bv) { bv = ov; bi = oi; }
                }
                if ((tid & 31) == 0) { wv_[tid >> 5] = bv; wi_[tid >> 5] = bi; }
                __syncthreads();
                if (tid == 0) {
                    float mv = wv_[0]; int mi = wi_[0];
                    #pragma unroll
                    for (int k = 1; k < 8; ++k)
                        if (wv_[k] > mv) { mv = wv_[k]; mi = wi_[k]; }
                    cand[mi] = -FLT_MAX;
                    negsum += fmaxf(mv, 0.f);
                }
                __syncthreads();
            }
            __syncthreads();
        }
        if (tid == 0) g_row[b] = negsum * 0.1f;
    }
}

// =====================================================================
// Pass 3: scalar reduction
// =====================================================================
__global__ void k_final(const int* __restrict__ label, float* __restrict__ out) {
    __shared__ float sp[256], sn[256];
    __shared__ int   cp_[256], cn_[256];
    int tid = threadIdx.x;
    float ps = 0.f, ns = 0.f;
    int pc = 0, nc = 0;
    for (int b = tid; b < Bsz; b += 256) {
        if (label[b] != -1) { ps += g_row[b]; pc++; }
        else                { ns += g_row[b]; nc++; }
    }
    sp[tid] = ps; sn[tid] = ns; cp_[tid] = pc; cn_[tid] = nc;
    __syncthreads();
    for (int o = 128; o > 0; o >>= 1) {
        if (tid < o) {
            sp[tid] += sp[tid + o]; sn[tid] += sn[tid + o];
            cp_[tid] += cp_[tid + o]; cn_[tid] += cn_[tid + o];
        }
        __syncthreads();
    }
    if (tid == 0) {
        float r = 0.f;
        if (cp_[0] > 0) r += sp[0] / (float)cp_[0];
        if (cn_[0] > 0) r += sn[0] / (float)cn_[0];
        out[0] = r;
    }
}

// =====================================================================
extern "C" void kernel_launch(void* const* d_in, const int* in_sizes, int n_in,
                              void* d_out, int out_size) {
    const float* p   = (const float*)d_in[0];
    const float* q   = (const float*)d_in[1];
    const float* mk  = (const float*)d_in[2];
    const int*   lab = (const int*)d_in[3];
    float* out = (float*)d_out;

    const int SMEM1 = 512 + 2 * 36864;   // 74240 (Csh 68096 fits in stage region)
    cudaFuncSetAttribute(k_pass1,  cudaFuncAttributeMaxDynamicSharedMemorySize, SMEM1);
    cudaFuncSetAttribute(k_pass1b, cudaFuncAttributeMaxDynamicSharedMemorySize, SMEM1);

    k_convert<<<33280, 256>>>(p, q);
    k_scan<<<1, 1024>>>(mk);
    k_gather<<<MCAP, 128>>>(q);
    dim3 g1(8, NT2);
    k_pass1<<<g1, 256, SMEM1>>>(mk, lab);
    dim3 g1b(8, MT2);
    k_pass1b<<<g1b, 256, SMEM1>>>(lab);
    k_pass2<<<Bsz, 256>>>(p, q, mk, lab);
    k_final<<<1, 256>>>(lab, out);
}

// round 10
// speedup vs baseline: 1.3601x; 1.1186x over previous
#include <cuda_runtime.h>
#include <cuda_bf16.h>
#include <cstdint>
#include <cfloat>
#include <math.h>

#define Bsz 1024
#define Qsz 65536
#define Dsz 512
#define MARGINf 0.4f
#define SCALEf 32.0f
#define K2f 46.166241308446828f   /* 32*log2(e) */
#define NT2 512                   /* q-tiles of 128 slots (q0 GEMM) */
#define MT2 64                    /* masked-compact tiles of 128 */
#define MCAP 8192
#define CPAD 133

// ---------------- static device scratch (no allocations) ----------------
__device__ __align__(16) __nv_bfloat16 g_qbf[(size_t)Qsz * Dsz];     // q0 bf16, 64 MB
__device__ __align__(16) __nv_bfloat16 g_pbf[Bsz * Dsz];             // 1 MB
__device__ __align__(16) __nv_bfloat16 g_qm[(size_t)MCAP * Dsz];     // masked q1 rows, 8 MB
__device__ int   g_midx[MCAP];
__device__ int   g_mcount;
__device__ float g_s1 [(size_t)NT2 * Bsz];
__device__ float g_s1m[(size_t)NT2 * Bsz];
__device__ float g_s2b[(size_t)MT2 * Bsz];
__device__ float g_t1 [(size_t)NT2 * 256 * 10];
__device__ float g_t1u[(size_t)NT2 * 256 * 10];
__device__ float g_t2b[(size_t)MT2 * 256 * 10];
__device__ float g_row[Bsz];

// ---------------- helpers ----------------
__device__ __forceinline__ float ex2f(float x) {
    float y;
    asm("ex2.approx.ftz.f32 %0, %1;" : "=f"(y) : "f"(x));
    return y;
}

__device__ __forceinline__ void ins10(float (&t)[10], float v) {
    if (v <= t[9]) return;
    #pragma unroll
    for (int i = 0; i < 10; ++i) {
        float a  = t[i];
        float hi = fmaxf(a, v);
        float lo = fminf(a, v);
        t[i] = hi;
        v    = lo;
    }
}

#define MMA16816(ac, Ar, b0, b1)                                                        \
    asm volatile(                                                                       \
        "mma.sync.aligned.m16n8k16.row.col.f32.bf16.bf16.f32 "                          \
        "{%0,%1,%2,%3},{%4,%5,%6,%7},{%8,%9},{%0,%1,%2,%3};"                            \
        : "+f"(ac[0]), "+f"(ac[1]), "+f"(ac[2]), "+f"(ac[3])                            \
        : "r"(Ar[0]), "r"(Ar[1]), "r"(Ar[2]), "r"(Ar[3]), "r"(b0), "r"(b1))

// =====================================================================
// Pass 0a: fp32 -> bf16 staging for p and queue[0]
// =====================================================================
__global__ void k_convert(const float* __restrict__ p, const float* __restrict__ q) {
    int i = blockIdx.x * blockDim.x + threadIdx.x;
    const int PN4 = (Bsz * Dsz) / 4;
    const int TOT = PN4 + (Qsz * Dsz) / 4;
    if (i >= TOT) return;
    float4 v;
    __nv_bfloat162* dst;
    if (i < PN4) {
        v   = ((const float4*)p)[i];
        dst = (__nv_bfloat162*)g_pbf + (size_t)i * 2;
    } else {
        size_t j = (size_t)i - PN4;
        v   = ((const float4*)q)[j];
        dst = (__nv_bfloat162*)g_qbf + j * 2;
    }
    dst[0] = __floats2bfloat162_rn(v.x, v.y);
    dst[1] = __floats2bfloat162_rn(v.z, v.w);
}

// =====================================================================
// Pass 0b: compact masked slot indices — coalesced strided access.
// Compaction order is interleaved (deterministic); downstream consumers
// are order-insensitive set reductions.
// =====================================================================
__global__ void __launch_bounds__(1024) k_scan(const float* __restrict__ maskp) {
    __shared__ int cnt[1024];
    int t = threadIdx.x;
    int local = 0;
    #pragma unroll 4
    for (int i = 0; i < 64; ++i) local += (maskp[i * 1024 + t] != 0.f);
    cnt[t] = local;
    __syncthreads();
    for (int o = 1; o < 1024; o <<= 1) {
        int v = (t >= o) ? cnt[t - o] : 0;
        __syncthreads();
        cnt[t] += v;
        __syncthreads();
    }
    if (t == 1023) g_mcount = cnt[1023] < MCAP ? cnt[1023] : MCAP;
    int j = cnt[t] - local;
    for (int i = 0; i < 64; ++i) {
        int idx = i * 1024 + t;
        if (maskp[idx] != 0.f) {
            if (j < MCAP) g_midx[j] = idx;
            ++j;
        }
    }
}

// =====================================================================
// Pass 0c: gather+convert masked q1 rows (zero-fill beyond count)
// =====================================================================
__global__ void __launch_bounds__(128) k_gather(const float* __restrict__ q) {
    int j = blockIdx.x, t = threadIdx.x;
    int count = g_mcount;
    __nv_bfloat162* dst = (__nv_bfloat162*)(g_qm + (size_t)j * Dsz);
    if (j < count) {
        const float4* src =
            (const float4*)(q + (size_t)Qsz * Dsz + (size_t)g_midx[j] * Dsz);
        float4 v = src[t];
        dst[t * 2]     = __floats2bfloat162_rn(v.x, v.y);
        dst[t * 2 + 1] = __floats2bfloat162_rn(v.z, v.w);
    } else {
        __nv_bfloat162 z = __floats2bfloat162_rn(0.f, 0.f);
        dst[t * 2]     = z;
        dst[t * 2 + 1] = z;
    }
}

// =====================================================================
// Merged Pass 1 + 1b: bf16 GEMM (128x128xK512) + fused epilogue.
// grid (8 b-tiles [fast], 512 q0-tiles + 64 masked tiles), 256 threads.
// 3-stage cp.async pipeline, single __syncthreads per K-step.
// smem: [0,512) mask[128]; [512,+110592) 3 x 36864B stages (reused as Csh).
// =====================================================================
__global__ void __launch_bounds__(256) k_mm(const float* __restrict__ maskp,
                                            const int* __restrict__ label) {
    extern __shared__ char sm_[];
    float* maskSh = (float*)sm_;
    char*  buf    = sm_ + 512;
    const int RS  = 144;
    const int ASZ = 128 * RS;     // 18432
    const int STG = 2 * ASZ;      // 36864 per stage

    int tid = threadIdx.x, lane = tid & 31, w = tid >> 5;
    int wm = w & 3, wn = w >> 2;
    int bx = blockIdx.x, by = blockIdx.y;
    bool isB = (by >= NT2);
    int count = g_mcount;
    int jb = isB ? (by - NT2) * 128 : 0;

    if (isB && jb >= count) {                 // dead masked tile
        if (bx == 0) {
            int byb = by - NT2;
            for (int r = tid; r < Bsz; r += 256) g_s2b[(size_t)byb * Bsz + r] = 0.f;
            for (int i = tid; i < 2560; i += 256) g_t2b[(size_t)byb * 2560 + i] = -FLT_MAX;
        }
        return;
    }

    const __nv_bfloat16* gp = g_pbf + (size_t)bx * 128 * Dsz;
    const __nv_bfloat16* gq = isB ? (g_qm + (size_t)jb * Dsz)
                                  : (g_qbf + (size_t)by * 128 * Dsz);
    if (!isB && tid < 128) maskSh[tid] = maskp[by * 128 + tid];

    uint32_t sbase = (uint32_t)__cvta_generic_to_shared(buf);

    // precomputed per-thread copy offsets (A and B share the pattern)
    uint32_t off[4], gof[4];
    #pragma unroll
    for (int t = 0; t < 4; ++t) {
        int i = tid + t * 256;
        int r = i >> 3, c = i & 7;
        off[t] = r * RS + c * 16;       // smem byte offset within tile
        gof[t] = r * 1024 + c * 16;     // gmem byte offset within tile (r*Dsz*2)
    }

    float acc[2][8][4];
    #pragma unroll
    for (int mt = 0; mt < 2; ++mt)
        #pragma unroll
        for (int nt = 0; nt < 8; ++nt)
            #pragma unroll
            for (int j = 0; j < 4; ++j) acc[mt][nt][j] = 0.f;

    auto issue = [&](int ks, int s) {
        uint32_t ab = sbase + s * STG;
        uint32_t bb = ab + ASZ;
        const char* gA = (const char*)gp + ks * 128;   // 64 bf16 = 128 B per K-step
        const char* gB = (const char*)gq + ks * 128;
        #pragma unroll
        for (int t = 0; t < 4; ++t) {
            asm volatile("cp.async.cg.shared.global [%0],[%1],16;"
                         :: "r"(ab + off[t]), "l"(gA + gof[t]));
            asm volatile("cp.async.cg.shared.global [%0],[%1],16;"
                         :: "r"(bb + off[t]), "l"(gB + gof[t]));
        }
        asm volatile("cp.async.commit_group;");
    };

    auto compute = [&](int s) {
        uint32_t ab = sbase + s * STG;
        uint32_t bb = ab + ASZ;
        uint32_t aBase = ab + (wm * 32 + (lane & 15)) * RS + (lane >> 4) * 16;
        int bq = lane >> 3;
        uint32_t bPart = bb + (wn * 64 + (bq >> 1) * 8 + (lane & 7)) * RS + (bq & 1) * 16;
        #pragma unroll
        for (int kk = 0; kk < 4; ++kk) {
            uint32_t A[2][4];
            #pragma unroll
            for (int mt = 0; mt < 2; ++mt) {
                uint32_t ad = aBase + mt * 16 * RS + kk * 32;
                asm volatile("ldmatrix.sync.aligned.m8n8.x4.shared.b16 {%0,%1,%2,%3},[%4];"
                             : "=r"(A[mt][0]), "=r"(A[mt][1]), "=r"(A[mt][2]), "=r"(A[mt][3])
                             : "r"(ad));
            }
            #pragma unroll
            for (int np = 0; np < 4; ++np) {
                uint32_t bd = bPart + np * 16 * RS + kk * 32;
                uint32_t B0, B1, B2, B3;
                asm volatile("ldmatrix.sync.aligned.m8n8.x4.shared.b16 {%0,%1,%2,%3},[%4];"
                             : "=r"(B0), "=r"(B1), "=r"(B2), "=r"(B3) : "r"(bd));
                #pragma unroll
                for (int mt = 0; mt < 2; ++mt) {
                    MMA16816(acc[mt][2 * np],     A[mt], B0, B1);
                    MMA16816(acc[mt][2 * np + 1], A[mt], B2, B3);
                }
            }
        }
    };

    // 3-stage pipeline, 1 barrier per K-step
    issue(0, 0);
    issue(1, 1);
    #pragma unroll 1
    for (int ks = 0; ks < 8; ++ks) {
        int s = ks % 3;
        if (ks < 7) asm volatile("cp.async.wait_group 1;");
        else        asm volatile("cp.async.wait_group 0;");
        __syncthreads();
        compute(s);
        if (ks < 6) issue(ks + 2, (ks + 2) % 3);
    }
    __syncthreads();   // protect stage buffers before Csh reuse

    // ---- C tile -> smem (68096 B <= 110592 B stage region) ----
    float* Csh = (float*)buf;
    #pragma unroll
    for (int mt = 0; mt < 2; ++mt)
        #pragma unroll
        for (int nt = 0; nt < 8; ++nt) {
            int r = wm * 32 + mt * 16 + (lane >> 2);
            int c = wn * 64 + nt * 8 + 2 * (lane & 3);
            Csh[r * CPAD + c]           = acc[mt][nt][0];
            Csh[r * CPAD + c + 1]       = acc[mt][nt][1];
            Csh[(r + 8) * CPAD + c]     = acc[mt][nt][2];
            Csh[(r + 8) * CPAD + c + 1] = acc[mt][nt][3];
        }
    __syncthreads();

    if (!isB) {
        // tid<128 : s1 (all cols) + top10 all; tid>=128 : s1m (masked) + top10 unmasked
        int  r     = tid & 127;
        bool roleB = (tid >= 128);
        int  gb    = bx * 128 + r;
        bool neg   = (label[gb] == -1);

        float s = 0.f;
        float top[10];
        #pragma unroll
        for (int i = 0; i < 10; ++i) top[i] = -FLT_MAX;

        const float* Crow = Csh + r * CPAD;
        for (int c = 0; c < 128; ++c) {
            float v = Crow[c];
            bool  mskd = (maskSh[c] != 0.f);
            if (!roleB) {
                s += ex2f(K2f * v);
                if (neg) ins10(top, v);
            } else {
                if (mskd) s += ex2f(K2f * v);
                else if (neg) ins10(top, v);
            }
        }

        size_t si = (size_t)by * Bsz + gb;
        if (!roleB) g_s1[si] = s; else g_s1m[si] = s;
        if (neg) {
            size_t ti = ((size_t)by * 256 + (gb >> 2)) * 10;
            float* gt_ = roleB ? g_t1u : g_t1;
            #pragma unroll
            for (int i = 0; i < 10; ++i) gt_[ti + i] = top[i];
        }
    } else if (tid < 128) {
        int  byb = by - NT2;
        int  r   = tid;
        int  gb  = bx * 128 + r;
        bool neg = (label[gb] == -1);
        int  nvalid = count - jb; if (nvalid > 128) nvalid = 128;

        float s = 0.f;
        float top[10];
        #pragma unroll
        for (int i = 0; i < 10; ++i) top[i] = -FLT_MAX;

        const float* Crow = Csh + r * CPAD;
        for (int c = 0; c < nvalid; ++c) {
            float v = Crow[c];
            s += ex2f(K2f * v);
            if (neg) ins10(top, v);
        }
        g_s2b[(size_t)byb * Bsz + gb] = s;
        if (neg) {
            size_t ti = ((size_t)byb * 256 + (gb >> 2)) * 10;
            #pragma unroll
            for (int i = 0; i < 10; ++i) g_t2b[ti + i] = top[i];
        }
    }
}

// =====================================================================
// Pass 2: per-row merge
// =====================================================================
__global__ void __launch_bounds__(256) k_pass2(const float* __restrict__ p,
                                               const float* __restrict__ q,
                                               const float* __restrict__ maskp,
                                               const int* __restrict__ label) {
    __shared__ float red[256];
    __shared__ float red2[256];
    __shared__ float red3[256];
    __shared__ float cand[2560];
    __shared__ float wv_[8];
    __shared__ int   wi_[8];

    int b = blockIdx.x, tid = threadIdx.x;
    int lab = label[b];

    if (lab != -1) {
        float s1 = 0.f, s1m = 0.f, s2b = 0.f;
        for (int t = tid; t < NT2; t += 256) {
            s1  += g_s1 [(size_t)t * Bsz + b];
            s1m += g_s1m[(size_t)t * Bsz + b];
            if (t < MT2) s2b += g_s2b[(size_t)t * Bsz + b];
        }
        red[tid] = s1; red2[tid] = s1m; red3[tid] = s2b;
        __syncthreads();
        for (int o = 128; o > 0; o >>= 1) {
            if (tid < o) {
                red[tid]  += red[tid + o];
                red2[tid] += red2[tid + o];
                red3[tid] += red3[tid + o];
            }
            __syncthreads();
        }
        float S1 = red[0];
        float S2 = red[0] - red2[0] + red3[0];
        __syncthreads();

        float d1 = 0.f, d2 = 0.f;
        float mk = maskp[lab];
        const float* pr = p + (size_t)b * Dsz;
        const float* q0 = q + (size_t)lab * Dsz;
        const float* q1 = q0 + (size_t)Qsz * Dsz;
        for (int d = tid; d < Dsz; d += 256) {
            float pv = pr[d], a0 = q0[d], a1 = q1[d];
            float wv = mk * a1 + (1.f - mk) * a0;
            d1 += pv * a0;
            d2 += pv * wv;
        }
        red[tid] = d1; red2[tid] = d2;
        __syncthreads();
        for (int o = 128; o > 0; o >>= 1) {
            if (tid < o) { red[tid] += red[tid + o]; red2[tid] += red2[tid + o]; }
            __syncthreads();
        }
        if (tid == 0) {
            float gt1 = red[0], gt2 = red2[0];
            float sp1 = S1 - ex2f(K2f * gt1) + ex2f(K2f * (gt1 - MARGINf));
            float sp2 = S2 - ex2f(K2f * gt2) + ex2f(K2f * (gt2 - MARGINf));
            float ce1 = logf(sp1) - (gt1 - MARGINf) * SCALEf;
            float ce2 = logf(sp2) - (gt2 - MARGINf) * SCALEf;
            g_row[b] = ce1 + ce2;
        }
    } else {
        float negsum = 0.f;
        size_t base = (size_t)(b >> 2) * 10;
        for (int mat = 0; mat < 2; ++mat) {
            float top[10];
            #pragma unroll
            for (int i = 0; i < 10; ++i) top[i] = -FLT_MAX;
            int nlists = (mat == 0) ? NT2 : (NT2 + MT2);
            for (int t = tid; t < nlists; t += 256) {
                const float* L;
                if (mat == 0)        L = g_t1  + (size_t)t * 2560 + base;
                else if (t < NT2)    L = g_t1u + (size_t)t * 2560 + base;
                else                 L = g_t2b + (size_t)(t - NT2) * 2560 + base;
                #pragma unroll
                for (int i = 0; i < 10; ++i) {
                    float v = L[i];
                    if (v <= top[9]) break;   // lists sorted descending
                    ins10(top, v);
                }
            }
            #pragma unroll
            for (int i = 0; i < 10; ++i) cand[tid * 10 + i] = top[i];
            __syncthreads();

            for (int it = 0; it < 10; ++it) {
                float bv = -FLT_MAX; int bi = -1;
                #pragma unroll
                for (int j = 0; j < 10; ++j) {
                    float v = cand[tid * 10 + j];
                    if (v > bv) { bv = v; bi = tid * 10 + j; }
                }
                #pragma unroll
                for (int o = 16; o > 0; o >>= 1) {
                    float ov = __shfl_down_sync(0xffffffffu, bv, o);
                    int   oi = __shfl_down_sync(0xffffffffu, bi, o);
                    if (ov > bv) { bv = ov; bi = oi; }
                }
                if ((tid & 31) == 0) { wv_[tid >> 5] = bv; wi_[tid >> 5] = bi; }
                __syncthreads();
                if (tid == 0) {
                    float mv = wv_[0]; int mi = wi_[0];
                    #pragma unroll
                    for (int k = 1; k < 8; ++k)
                        if (wv_[k] > mv) { mv = wv_[k]; mi = wi_[k]; }
                    cand[mi] = -FLT_MAX;
                    negsum += fmaxf(mv, 0.f);
                }
                __syncthreads();
            }
            __syncthreads();
        }
        if (tid == 0) g_row[b] = negsum * 0.1f;
    }
}

// =====================================================================
// Pass 3: scalar reduction
// =====================================================================
__global__ void k_final(const int* __restrict__ label, float* __restrict__ out) {
    __shared__ float sp[256], sn[256];
    __shared__ int   cp_[256], cn_[256];
    int tid = threadIdx.x;
    float ps = 0.f, ns = 0.f;
    int pc = 0, nc = 0;
    for (int b = tid; b < Bsz; b += 256) {
        if (label[b] != -1) { ps += g_row[b]; pc++; }
        else                { ns += g_row[b]; nc++; }
    }
    sp[tid] = ps; sn[tid] = ns; cp_[tid] = pc; cn_[tid] = nc;
    __syncthreads();
    for (int o = 128; o > 0; o >>= 1) {
        if (tid < o) {
            sp[tid] += sp[tid + o]; sn[tid] += sn[tid + o];
            cp_[tid] += cp_[tid + o]; cn_[tid] += cn_[tid + o];
        }
        __syncthreads();
    }
    if (tid == 0) {
        float r = 0.f;
        if (cp_[0] > 0) r += sp[0] / (float)cp_[0];
        if (cn_[0] > 0) r += sn[0] / (float)cn_[0];
        out[0] = r;
    }
}

// =====================================================================
extern "C" void kernel_launch(void* const* d_in, const int* in_sizes, int n_in,
                              void* d_out, int out_size) {
    const float* p   = (const float*)d_in[0];
    const float* q   = (const float*)d_in[1];
    const float* mk  = (const float*)d_in[2];
    const int*   lab = (const int*)d_in[3];
    float* out = (float*)d_out;

    const int SMEM1 = 512 + 3 * 36864;   // 111104
    cudaFuncSetAttribute(k_mm, cudaFuncAttributeMaxDynamicSharedMemorySize, SMEM1);

    k_convert<<<33280, 256>>>(p, q);
    k_scan<<<1, 1024>>>(mk);
    k_gather<<<MCAP, 128>>>(q);
    dim3 g1(8, NT2 + MT2);
    k_mm<<<g1, 256, SMEM1>>>(mk, lab);
    k_pass2<<<Bsz, 256>>>(p, q, mk, lab);
    k_final<<<1, 256>>>(lab, out);
}